// round 14
// baseline (speedup 1.0000x reference)
#include <cuda_runtime.h>
#include <math.h>

// ---------------- Problem constants ----------------
#define BS      8192
#define NL      512
#define ML      32
#define DP      128     // D_PATH
#define G3      384     // 3*D_PATH
#define DR      256     // D_READ
#define NO      3

// GRU kernel tiling (R4/R12 configuration - measured fastest)
#define SPT     7           // samples per sg-thread
#define BT      28          // samples per chunk = 4*SPT
#define NCHUNK  293         // ceil(8192/28)
#define GRU_BLOCKS 148
#define GRU_THREADS 256     // 64 jt x 4 sg
#define NPART   (GRU_BLOCKS * 4)   // 592 BN partial slots

// ---------------- Device scratch ----------------
__device__ float g_flow[BS * DP];
__device__ float g_psum[NPART * DP];
__device__ float g_psumsq[NPART * DP];
__device__ float g_bnA[DP];
__device__ float g_bnB[DP];
__device__ int   g_maxbits;          // zero-initialized; atomicMax idempotent across replays
__device__ int   g_order[BS];

// ---------------- packed f32x2 helpers ----------------
__device__ __forceinline__ void fma2(unsigned long long& d,
                                     unsigned long long a,
                                     unsigned long long b) {
    asm("fma.rn.f32x2 %0, %1, %2, %3;" : "=l"(d) : "l"(a), "l"(b), "l"(d));
}
__device__ __forceinline__ unsigned long long pk(float lo, float hi) {
    unsigned long long r;
    asm("mov.b64 %0, {%1, %2};" : "=l"(r)
        : "r"(__float_as_uint(lo)), "r"(__float_as_uint(hi)));
    return r;
}
__device__ __forceinline__ unsigned long long splat(float a) {
    unsigned long long r;
    asm("mov.b64 %0, {%1, %1};" : "=l"(r) : "r"(__float_as_uint(a)));
    return r;
}
__device__ __forceinline__ float upksum(unsigned long long v) {
    float lo = __uint_as_float((unsigned)(v & 0xffffffffull));
    float hi = __uint_as_float((unsigned)(v >> 32));
    return lo + hi;
}
__device__ __forceinline__ float upklo(unsigned long long v) {
    return __uint_as_float((unsigned)(v & 0xffffffffull));
}
__device__ __forceinline__ float upkhi(unsigned long long v) {
    return __uint_as_float((unsigned)(v >> 32));
}

__device__ __forceinline__ float tanhap(float x) {
    float y;
    asm("tanh.approx.f32 %0, %1;" : "=f"(y) : "f"(x));
    return y;
}
__device__ __forceinline__ float sigm(float x) {
    return 0.5f * tanhap(0.5f * x) + 0.5f;
}
__device__ __forceinline__ float seluf(float x) {
    const float sc = 1.0507009873554805f;
    const float al = 1.6732632423543772f;
    return x > 0.f ? sc * x : sc * al * (expf(x) - 1.f);
}

// ---------------- fused max + hist/scan/scatter ----------------
__global__ void k_maxprep(const float* __restrict__ capa,
                          const int* __restrict__ hop) {
    if (blockIdx.x < 256) {
        int i = blockIdx.x * blockDim.x + threadIdx.x;
        int stride = 256 * 256;
        const float4* c4 = (const float4*)capa;
        float m = 0.f;
        for (int q = i; q < (BS * NL) / 4; q += stride) {
            float4 v = c4[q];
            m = fmaxf(m, fmaxf(fmaxf(v.x, v.y), fmaxf(v.z, v.w)));
        }
#pragma unroll
        for (int off = 16; off > 0; off >>= 1)
            m = fmaxf(m, __shfl_down_sync(0xffffffffu, m, off));
        if ((threadIdx.x & 31) == 0) atomicMax(&g_maxbits, __float_as_int(m));
    } else {
        __shared__ int cnt[33];
        __shared__ int off[33];
        int t = threadIdx.x;
        if (t < 33) cnt[t] = 0;
        __syncthreads();
        for (int b = t; b < BS; b += 256) atomicAdd(&cnt[hop[b]], 1);
        __syncthreads();
        if (t == 0) {
            int acc = 0;
            for (int h = 32; h >= 1; h--) { off[h] = acc; acc += cnt[h]; }
        }
        __syncthreads();
        for (int b = t; b < BS; b += 256) {
            int pos = atomicAdd(&off[hop[b]], 1);
            g_order[pos] = b;
        }
    }
}

// ---------------- GRU (R13 config: fused BN partials, no carry-forward) ----------------
__global__ void __launch_bounds__(GRU_THREADS, 1)
k_gru(const float* __restrict__ demand,
      const float* __restrict__ avail,
      const float* __restrict__ capa,
      const float* __restrict__ loss,
      const int*   __restrict__ path,
      const int*   __restrict__ hop,
      const float* __restrict__ w_ih,
      const float* __restrict__ w_hh,
      const float* __restrict__ b_ih,
      const float* __restrict__ b_hh)
{
    extern __shared__ float sm[];
    float* wsh = sm;                          // 49152 floats (192 KB)
    float* hbuf0 = sm + 49152;                // BT*DP
    float* hbuf1 = hbuf0 + BT * DP;           // BT*DP
    float* xbuf0 = hbuf1 + BT * DP;           // BT*4
    float* xbuf1 = xbuf0 + BT * 4;            // BT*4
    int*   sb    = (int*)(xbuf1 + BT * 4);
    int*   shop  = sb + BT;
    int*   smaxh = shop + BT;

    const int tid = threadIdx.x;
    const int jt = tid & 63;
    const int sg = tid >> 6;

    const float4* w4g = (const float4*)w_hh;
    for (int q = tid; q < G3 * 32; q += GRU_THREADS) {
        int j = q >> 5, k4 = q & 31;
        float4 v = __ldg(w4g + q);
        ((float4*)wsh)[(j << 5) + (k4 ^ (j & 31))] = v;
    }

    const float maxc = __int_as_float(g_maxbits);
    const float inv_maxc = 1.f / maxc;

    float wih[6][4], bihv[6], bhhv[6];
    int wbase4[6], jx[6];
#pragma unroll
    for (int dd = 0; dd < 2; dd++) {
#pragma unroll
        for (int g = 0; g < 3; g++) {
            int i = dd * 3 + g;
            int j = g * 128 + jt + dd * 64;
#pragma unroll
            for (int c = 0; c < 4; c++) wih[i][c] = __ldg(w_ih + j * 32 + 28 + c);
            bihv[i] = __ldg(b_ih + j);
            bhhv[i] = __ldg(b_hh + j);
            wbase4[i] = j << 5;
            jx[i] = j & 31;
        }
    }

    float bns[2] = {0.f, 0.f}, bnq[2] = {0.f, 0.f};

    for (int cidx = 0; cidx < 2; cidx++) {
        int chunk = (cidx == 0) ? (int)blockIdx.x : (NCHUNK - 1 - (int)blockIdx.x);
        if (cidx == 1 && chunk < GRU_BLOCKS) break;   // LPT pairing
        int base = chunk * BT;
        int cnt = min(BT, BS - base);

        if (tid == 0) *smaxh = 0;
        __syncthreads();
        int myb = -1, myhop = 0;
        if (tid < BT) {
            if (tid < cnt) { myb = g_order[base + tid]; myhop = hop[myb]; }
            sb[tid] = myb; shop[tid] = myhop;
            atomicMax(smaxh, myhop);
        }
        for (int q = tid; q < BT * DP; q += GRU_THREADS) hbuf0[q] = 0.f;
        __syncthreads();
        if (tid < cnt) hbuf0[tid * DP + (DP - 1)] = demand[myb] * inv_maxc;
        int maxh = *smaxh;

        float f0 = 0.f, f1 = 0.f, f2 = 0.f, f3 = 0.f;
        if (tid < cnt && myhop > 0) {
            int l = path[myb * ML + 0];
            float a = avail[myb * NL + l];
            float c = capa[myb * NL + l];
            float lo = loss[myb * NL + l];
            xbuf0[tid * 4 + 0] = a * inv_maxc;
            xbuf0[tid * 4 + 1] = c * inv_maxc;
            xbuf0[tid * 4 + 2] = a / c;
            xbuf0[tid * 4 + 3] = lo;
        }
        if (tid < cnt && myhop > 1) {
            int l = path[myb * ML + 1];
            float a = avail[myb * NL + l];
            float c = capa[myb * NL + l];
            f0 = a * inv_maxc; f1 = c * inv_maxc;
            f2 = a / c; f3 = loss[myb * NL + l];
        }
        __syncthreads();

        for (int t = 0; t < maxh; t++) {
            float* hR = (t & 1) ? hbuf1 : hbuf0;
            float* hW = (t & 1) ? hbuf0 : hbuf1;
            float* xR = (t & 1) ? xbuf1 : xbuf0;
            float* xW = (t & 1) ? xbuf0 : xbuf1;

            if (tid < cnt && t + 1 < myhop) {
                xW[tid * 4 + 0] = f0; xW[tid * 4 + 1] = f1;
                xW[tid * 4 + 2] = f2; xW[tid * 4 + 3] = f3;
            }
            if (tid < cnt && t + 2 < myhop) {
                int l = path[myb * ML + t + 2];
                float a = avail[myb * NL + l];
                float c = capa[myb * NL + l];
                f0 = a * inv_maxc; f1 = c * inv_maxc;
                f2 = a / c; f3 = loss[myb * NL + l];
            }

            unsigned long long acc2[6][SPT];
#pragma unroll
            for (int i = 0; i < 6; i++)
#pragma unroll
                for (int s = 0; s < SPT; s++) acc2[i][s] = 0ull;

            const ulonglong2* hsp = (const ulonglong2*)hR;
            const ulonglong2* wsp = (const ulonglong2*)wsh;
            const int sbase = sg * SPT * 32;
#pragma unroll 2
            for (int k4 = 0; k4 < 32; k4++) {
                ulonglong2 wv[6];
#pragma unroll
                for (int i = 0; i < 6; i++)
                    wv[i] = wsp[wbase4[i] + (k4 ^ jx[i])];
#pragma unroll
                for (int ss = 0; ss < SPT; ss++) {
                    ulonglong2 hv = hsp[sbase + ss * 32 + k4];  // broadcast
#pragma unroll
                    for (int i = 0; i < 6; i++) {
                        fma2(acc2[i][ss], wv[i].x, hv.x);
                        fma2(acc2[i][ss], wv[i].y, hv.y);
                    }
                }
            }

#pragma unroll
            for (int ss = 0; ss < SPT; ss++) {
                int s = sg * SPT + ss;
                int hp = shop[s];
                if (t < hp) {
                    float x0 = xR[s * 4 + 0], x1 = xR[s * 4 + 1];
                    float x2 = xR[s * 4 + 2], x3 = xR[s * 4 + 3];
#pragma unroll
                    for (int dd = 0; dd < 2; dd++) {
                        int d = jt + dd * 64;
                        int ir = dd * 3 + 0, iz = dd * 3 + 1, in_ = dd * 3 + 2;
                        float ar = upksum(acc2[ir][ss]);
                        float az = upksum(acc2[iz][ss]);
                        float an = upksum(acc2[in_][ss]);
                        float gr = bihv[ir] + wih[ir][0] * x0 + wih[ir][1] * x1
                                 + wih[ir][2] * x2 + wih[ir][3] * x3 + ar + bhhv[ir];
                        float gz = bihv[iz] + wih[iz][0] * x0 + wih[iz][1] * x1
                                 + wih[iz][2] * x2 + wih[iz][3] * x3 + az + bhhv[iz];
                        float gni = bihv[in_] + wih[in_][0] * x0 + wih[in_][1] * x1
                                  + wih[in_][2] * x2 + wih[in_][3] * x3;
                        float gnh = an + bhhv[in_];
                        float r = sigm(gr);
                        float z = sigm(gz);
                        float n = tanhap(gni + r * gnh);
                        float hold = hR[s * DP + d];
                        float hnew = (1.f - z) * n + z * hold;
                        hW[s * DP + d] = hnew;
                        if (t == hp - 1) {
                            g_flow[sb[s] * DP + d] = hnew;
                            bns[dd] += hnew;
                            bnq[dd] += hnew * hnew;
                        }
                    }
                }
            }
            __syncthreads();
        }
    }

    int slot = ((int)blockIdx.x * 4 + sg) * DP;
    g_psum[slot + jt]      = bns[0];
    g_psum[slot + jt + 64] = bns[1];
    g_psumsq[slot + jt]      = bnq[0];
    g_psumsq[slot + jt + 64] = bnq[1];
}

// ---------------- BN final: reduce 592 partials ----------------
__global__ void k_bnfinal(const float* __restrict__ gamma, const float* __restrict__ beta) {
    __shared__ float ssum[8 * DP];
    __shared__ float ssq[8 * DP];
    int tid = threadIdx.x;
    int d = tid & 127;
    int seg = tid >> 7;
    float s = 0.f, s2 = 0.f;
    for (int blk = seg; blk < NPART; blk += 8) {
        s += g_psum[blk * DP + d];
        s2 += g_psumsq[blk * DP + d];
    }
    ssum[seg * DP + d] = s;
    ssq[seg * DP + d] = s2;
    __syncthreads();
    if (tid < DP) {
        float ts = 0.f, ts2 = 0.f;
#pragma unroll
        for (int g = 0; g < 8; g++) {
            ts += ssum[g * DP + tid];
            ts2 += ssq[g * DP + tid];
        }
        float mean = ts * (1.f / BS);
        float var = ts2 * (1.f / BS) - mean * mean;
        float rstd = rsqrtf(var + 1e-5f);
        float A = rstd * gamma[tid];
        g_bnA[tid] = A;
        g_bnB[tid] = beta[tid] - mean * A;
    }
}

// ---------------- fused readout, 32x256 tile, 3 CTAs/SM ----------------
// grid (BS/32, NO) = 768 blocks, 256 threads.
// h1 pairs: h1p[c*17 + trow*2 + mp]; smem 34816+32768+2048+4096 = 73728 B.
#define RD_SMEM (256 * 17 * 8 + 16 * 256 * 8 + 16 * 32 * 4 + 32 * 32 * 4)
__global__ void __launch_bounds__(256, 3)
k_read(const float* __restrict__ rW1, const float* __restrict__ rb1,
       const float* __restrict__ rW2, const float* __restrict__ rb2,
       const float* __restrict__ rW3, const float* __restrict__ rb3,
       float* __restrict__ out) {
    extern __shared__ char smraw[];
    unsigned long long* h1p = (unsigned long long*)smraw;              // 256*17 ull
    unsigned long long* Bsp = (unsigned long long*)(smraw + 34816);    // 16*256 ull
    float* As  = (float*)(smraw + 34816 + 32768);                      // 16*32
    float* red = (float*)(smraw + 34816 + 32768 + 2048);               // 32*32

    int tid = threadIdx.x;
    int m0 = blockIdx.x * 32, u = blockIdx.y;
    int trow = tid >> 5, tcol = tid & 31;

    unsigned long long acc2[2][8];
#pragma unroll
    for (int i = 0; i < 2; i++)
#pragma unroll
        for (int j = 0; j < 8; j++) acc2[i][j] = 0ull;

    // ---- phase 1: h1 tile (32x256) ----
    const float* B1 = rW1 + u * DP * DR;
    for (int k0 = 0; k0 < DP; k0 += 16) {
        {   // A tile 32x16 (BN on load): each thread one float2
            int m = tid >> 3, kq = tid & 7;
            float2 v = *(const float2*)(g_flow + (m0 + m) * DP + k0 + kq * 2);
            int kb = k0 + kq * 2;
            As[(kq * 2 + 0) * 32 + m] = v.x * g_bnA[kb + 0] + g_bnB[kb + 0];
            As[(kq * 2 + 1) * 32 + m] = v.y * g_bnA[kb + 1] + g_bnB[kb + 1];
        }
#pragma unroll
        for (int r = 0; r < 4; r++) {   // B1 tile splatted 16x256
            int idx = r * 256 + tid;
            int k = idx >> 6, nq = idx & 63;
            float4 v = *(const float4*)(B1 + (k0 + k) * DR + nq * 4);
            Bsp[k * 256 + nq * 4 + 0] = splat(v.x);
            Bsp[k * 256 + nq * 4 + 1] = splat(v.y);
            Bsp[k * 256 + nq * 4 + 2] = splat(v.z);
            Bsp[k * 256 + nq * 4 + 3] = splat(v.w);
        }
        __syncthreads();
#pragma unroll
        for (int kk = 0; kk < 16; kk++) {
            ulonglong2 ap2 = *(const ulonglong2*)&As[kk * 32 + trow * 4];
            unsigned long long ap[2] = {ap2.x, ap2.y};
#pragma unroll
            for (int jj = 0; jj < 4; jj++) {
                ulonglong2 bv = *(const ulonglong2*)&Bsp[kk * 256 + tcol * 2 + 64 * jj];
#pragma unroll
                for (int mp = 0; mp < 2; mp++) {
                    fma2(acc2[mp][jj * 2 + 0], ap[mp], bv.x);
                    fma2(acc2[mp][jj * 2 + 1], ap[mp], bv.y);
                }
            }
        }
        __syncthreads();
    }
#pragma unroll
    for (int mp = 0; mp < 2; mp++) {
#pragma unroll
        for (int j = 0; j < 8; j++) {
            int c = tcol * 2 + 64 * (j >> 1) + (j & 1);
            float b = rb1[u * DR + c];
            float lo = seluf(upklo(acc2[mp][j]) + b);
            float hi = seluf(upkhi(acc2[mp][j]) + b);
            h1p[c * 17 + trow * 2 + mp] = pk(lo, hi);
        }
    }
    __syncthreads();

    // ---- phase 2: h2 + y ----
    const float* B2 = rW2 + u * DR * DR;
    float w3v[8];
#pragma unroll
    for (int j = 0; j < 8; j++)
        w3v[j] = __ldg(rW3 + u * DR + tcol * 2 + 64 * (j >> 1) + (j & 1));

#pragma unroll
    for (int i = 0; i < 2; i++)
#pragma unroll
        for (int j = 0; j < 8; j++) acc2[i][j] = 0ull;

    for (int k0 = 0; k0 < DR; k0 += 16) {
#pragma unroll
        for (int r = 0; r < 4; r++) {   // B2 tile splatted 16x256
            int idx = r * 256 + tid;
            int k = idx >> 6, nq = idx & 63;
            float4 v = *(const float4*)(B2 + (k0 + k) * DR + nq * 4);
            Bsp[k * 256 + nq * 4 + 0] = splat(v.x);
            Bsp[k * 256 + nq * 4 + 1] = splat(v.y);
            Bsp[k * 256 + nq * 4 + 2] = splat(v.z);
            Bsp[k * 256 + nq * 4 + 3] = splat(v.w);
        }
        __syncthreads();
#pragma unroll
        for (int kk = 0; kk < 16; kk++) {
            int kg = k0 + kk;
            unsigned long long ap[2];
#pragma unroll
            for (int mp = 0; mp < 2; mp++)
                ap[mp] = h1p[kg * 17 + trow * 2 + mp];   // warp broadcast
#pragma unroll
            for (int jj = 0; jj < 4; jj++) {
                ulonglong2 bv = *(const ulonglong2*)&Bsp[kk * 256 + tcol * 2 + 64 * jj];
#pragma unroll
                for (int mp = 0; mp < 2; mp++) {
                    fma2(acc2[mp][jj * 2 + 0], ap[mp], bv.x);
                    fma2(acc2[mp][jj * 2 + 1], ap[mp], bv.y);
                }
            }
        }
        __syncthreads();
    }
#pragma unroll
    for (int mp = 0; mp < 2; mp++) {
#pragma unroll
        for (int e = 0; e < 2; e++) {
            int i = trow * 4 + mp * 2 + e;
            float p = 0.f;
#pragma unroll
            for (int j = 0; j < 8; j++) {
                int c = tcol * 2 + 64 * (j >> 1) + (j & 1);
                float v = e ? upkhi(acc2[mp][j]) : upklo(acc2[mp][j]);
                float h2 = seluf(v + rb2[u * DR + c]);
                p += h2 * w3v[j];
            }
            red[i * 32 + tcol] = p;
        }
    }
    __syncthreads();
    if (tid < 32) {
        float y = rb3[u];
#pragma unroll
        for (int c = 0; c < 32; c++) y += red[tid * 32 + c];
        out[(m0 + tid) * NO + u] = y;
    }
}

// ---------------- launcher ----------------
extern "C" void kernel_launch(void* const* d_in, const int* in_sizes, int n_in,
                              void* d_out, int out_size) {
    const float* demand = (const float*)d_in[0];
    const float* avail  = (const float*)d_in[1];
    const float* capa   = (const float*)d_in[2];
    const float* loss   = (const float*)d_in[3];
    const int*   path   = (const int*)d_in[4];
    const int*   hop    = (const int*)d_in[5];
    const float* w_ih   = (const float*)d_in[6];
    const float* w_hh   = (const float*)d_in[7];
    const float* b_ih   = (const float*)d_in[8];
    const float* b_hh   = (const float*)d_in[9];
    const float* gamma  = (const float*)d_in[10];
    const float* beta   = (const float*)d_in[11];
    const float* rW1    = (const float*)d_in[12];
    const float* rb1    = (const float*)d_in[13];
    const float* rW2    = (const float*)d_in[14];
    const float* rb2    = (const float*)d_in[15];
    const float* rW3    = (const float*)d_in[16];
    const float* rb3    = (const float*)d_in[17];
    float* out = (float*)d_out;

    const int GRU_SMEM = (49152 + 2 * BT * DP + 2 * BT * 4) * 4
                       + (2 * BT + 1) * 4 + 256;
    cudaFuncSetAttribute(k_gru, cudaFuncAttributeMaxDynamicSharedMemorySize, GRU_SMEM);
    cudaFuncSetAttribute(k_read, cudaFuncAttributeMaxDynamicSharedMemorySize, RD_SMEM);

    k_maxprep<<<257, 256>>>(capa, hop);                    // idx 0
    k_gru<<<GRU_BLOCKS, GRU_THREADS, GRU_SMEM>>>(          // idx 1
        demand, avail, capa, loss, path, hop, w_ih, w_hh, b_ih, b_hh);
    k_bnfinal<<<1, 1024>>>(gamma, beta);                   // idx 2
    {
        dim3 gr(BS / 32, NO);
        k_read<<<gr, 256, RD_SMEM>>>(rW1, rb1, rW2, rb2, rW3, rb3, out);  // idx 3
    }
}

// round 16
// speedup vs baseline: 1.2423x; 1.2423x over previous
#include <cuda_runtime.h>
#include <math.h>

// ---------------- Problem constants ----------------
#define BS      8192
#define NL      512
#define ML      32
#define DP      128     // D_PATH
#define G3      384     // 3*D_PATH
#define DR      256     // D_READ
#define NO      3

// GRU kernel tiling (R4/R13 configuration - measured fastest)
#define SPT     7
#define BT      28
#define NCHUNK  293
#define GRU_BLOCKS 148
#define GRU_THREADS 256
#define NPART   (GRU_BLOCKS * 4)

// ---------------- Device scratch ----------------
__device__ float g_flow[BS * DP];
__device__ float g_psum[NPART * DP];
__device__ float g_psumsq[NPART * DP];
__device__ float g_bnA[DP];
__device__ float g_bnB[DP];
__device__ int   g_maxbits;
__device__ int   g_order[BS];

// ---------------- packed f32x2 helpers ----------------
__device__ __forceinline__ void fma2(unsigned long long& d,
                                     unsigned long long a,
                                     unsigned long long b) {
    asm("fma.rn.f32x2 %0, %1, %2, %3;" : "=l"(d) : "l"(a), "l"(b), "l"(d));
}
__device__ __forceinline__ unsigned long long pk(float lo, float hi) {
    unsigned long long r;
    asm("mov.b64 %0, {%1, %2};" : "=l"(r)
        : "r"(__float_as_uint(lo)), "r"(__float_as_uint(hi)));
    return r;
}
__device__ __forceinline__ unsigned long long splat(float a) {
    unsigned long long r;
    asm("mov.b64 %0, {%1, %1};" : "=l"(r) : "r"(__float_as_uint(a)));
    return r;
}
__device__ __forceinline__ float upksum(unsigned long long v) {
    float lo = __uint_as_float((unsigned)(v & 0xffffffffull));
    float hi = __uint_as_float((unsigned)(v >> 32));
    return lo + hi;
}
__device__ __forceinline__ float upklo(unsigned long long v) {
    return __uint_as_float((unsigned)(v & 0xffffffffull));
}
__device__ __forceinline__ float upkhi(unsigned long long v) {
    return __uint_as_float((unsigned)(v >> 32));
}

__device__ __forceinline__ float tanhap(float x) {
    float y;
    asm("tanh.approx.f32 %0, %1;" : "=f"(y) : "f"(x));
    return y;
}
__device__ __forceinline__ float sigm(float x) {
    return 0.5f * tanhap(0.5f * x) + 0.5f;
}
__device__ __forceinline__ float seluf(float x) {
    const float sc = 1.0507009873554805f;
    const float al = 1.6732632423543772f;
    return x > 0.f ? sc * x : sc * al * (expf(x) - 1.f);
}

// ---------------- cp.async helpers ----------------
__device__ __forceinline__ unsigned smaddr(const void* p) {
    unsigned r;
    asm("{ .reg .u64 t; cvta.to.shared.u64 t, %1; cvt.u32.u64 %0, t; }"
        : "=r"(r) : "l"(p));
    return r;
}
__device__ __forceinline__ void cpasync16(unsigned s, const void* g) {
    asm volatile("cp.async.ca.shared.global [%0], [%1], 16;" :: "r"(s), "l"(g));
}
__device__ __forceinline__ void cpcommit() {
    asm volatile("cp.async.commit_group;");
}
__device__ __forceinline__ void cpwait1() {
    asm volatile("cp.async.wait_group 1;" ::: "memory");
}
__device__ __forceinline__ void cpwait0() {
    asm volatile("cp.async.wait_group 0;" ::: "memory");
}

// ---------------- fused max + hist/scan/scatter ----------------
__global__ void k_maxprep(const float* __restrict__ capa,
                          const int* __restrict__ hop) {
    if (blockIdx.x < 256) {
        int i = blockIdx.x * blockDim.x + threadIdx.x;
        int stride = 256 * 256;
        const float4* c4 = (const float4*)capa;
        float m = 0.f;
        for (int q = i; q < (BS * NL) / 4; q += stride) {
            float4 v = c4[q];
            m = fmaxf(m, fmaxf(fmaxf(v.x, v.y), fmaxf(v.z, v.w)));
        }
#pragma unroll
        for (int off = 16; off > 0; off >>= 1)
            m = fmaxf(m, __shfl_down_sync(0xffffffffu, m, off));
        if ((threadIdx.x & 31) == 0) atomicMax(&g_maxbits, __float_as_int(m));
    } else {
        __shared__ int cnt[33];
        __shared__ int off[33];
        int t = threadIdx.x;
        if (t < 33) cnt[t] = 0;
        __syncthreads();
        for (int b = t; b < BS; b += 256) atomicAdd(&cnt[hop[b]], 1);
        __syncthreads();
        if (t == 0) {
            int acc = 0;
            for (int h = 32; h >= 1; h--) { off[h] = acc; acc += cnt[h]; }
        }
        __syncthreads();
        for (int b = t; b < BS; b += 256) {
            int pos = atomicAdd(&off[hop[b]], 1);
            g_order[pos] = b;
        }
    }
}

// ---------------- GRU (R13, measured fastest) ----------------
__global__ void __launch_bounds__(GRU_THREADS, 1)
k_gru(const float* __restrict__ demand,
      const float* __restrict__ avail,
      const float* __restrict__ capa,
      const float* __restrict__ loss,
      const int*   __restrict__ path,
      const int*   __restrict__ hop,
      const float* __restrict__ w_ih,
      const float* __restrict__ w_hh,
      const float* __restrict__ b_ih,
      const float* __restrict__ b_hh)
{
    extern __shared__ float sm[];
    float* wsh = sm;
    float* hbuf0 = sm + 49152;
    float* hbuf1 = hbuf0 + BT * DP;
    float* xbuf0 = hbuf1 + BT * DP;
    float* xbuf1 = xbuf0 + BT * 4;
    int*   sb    = (int*)(xbuf1 + BT * 4);
    int*   shop  = sb + BT;
    int*   smaxh = shop + BT;

    const int tid = threadIdx.x;
    const int jt = tid & 63;
    const int sg = tid >> 6;

    const float4* w4g = (const float4*)w_hh;
    for (int q = tid; q < G3 * 32; q += GRU_THREADS) {
        int j = q >> 5, k4 = q & 31;
        float4 v = __ldg(w4g + q);
        ((float4*)wsh)[(j << 5) + (k4 ^ (j & 31))] = v;
    }

    const float maxc = __int_as_float(g_maxbits);
    const float inv_maxc = 1.f / maxc;

    float wih[6][4], bihv[6], bhhv[6];
    int wbase4[6], jx[6];
#pragma unroll
    for (int dd = 0; dd < 2; dd++) {
#pragma unroll
        for (int g = 0; g < 3; g++) {
            int i = dd * 3 + g;
            int j = g * 128 + jt + dd * 64;
#pragma unroll
            for (int c = 0; c < 4; c++) wih[i][c] = __ldg(w_ih + j * 32 + 28 + c);
            bihv[i] = __ldg(b_ih + j);
            bhhv[i] = __ldg(b_hh + j);
            wbase4[i] = j << 5;
            jx[i] = j & 31;
        }
    }

    float bns[2] = {0.f, 0.f}, bnq[2] = {0.f, 0.f};

    for (int cidx = 0; cidx < 2; cidx++) {
        int chunk = (cidx == 0) ? (int)blockIdx.x : (NCHUNK - 1 - (int)blockIdx.x);
        if (cidx == 1 && chunk < GRU_BLOCKS) break;
        int base = chunk * BT;
        int cnt = min(BT, BS - base);

        if (tid == 0) *smaxh = 0;
        __syncthreads();
        int myb = -1, myhop = 0;
        if (tid < BT) {
            if (tid < cnt) { myb = g_order[base + tid]; myhop = hop[myb]; }
            sb[tid] = myb; shop[tid] = myhop;
            atomicMax(smaxh, myhop);
        }
        for (int q = tid; q < BT * DP; q += GRU_THREADS) hbuf0[q] = 0.f;
        __syncthreads();
        if (tid < cnt) hbuf0[tid * DP + (DP - 1)] = demand[myb] * inv_maxc;
        int maxh = *smaxh;

        float f0 = 0.f, f1 = 0.f, f2 = 0.f, f3 = 0.f;
        if (tid < cnt && myhop > 0) {
            int l = path[myb * ML + 0];
            float a = avail[myb * NL + l];
            float c = capa[myb * NL + l];
            float lo = loss[myb * NL + l];
            xbuf0[tid * 4 + 0] = a * inv_maxc;
            xbuf0[tid * 4 + 1] = c * inv_maxc;
            xbuf0[tid * 4 + 2] = a / c;
            xbuf0[tid * 4 + 3] = lo;
        }
        if (tid < cnt && myhop > 1) {
            int l = path[myb * ML + 1];
            float a = avail[myb * NL + l];
            float c = capa[myb * NL + l];
            f0 = a * inv_maxc; f1 = c * inv_maxc;
            f2 = a / c; f3 = loss[myb * NL + l];
        }
        __syncthreads();

        for (int t = 0; t < maxh; t++) {
            float* hR = (t & 1) ? hbuf1 : hbuf0;
            float* hW = (t & 1) ? hbuf0 : hbuf1;
            float* xR = (t & 1) ? xbuf1 : xbuf0;
            float* xW = (t & 1) ? xbuf0 : xbuf1;

            if (tid < cnt && t + 1 < myhop) {
                xW[tid * 4 + 0] = f0; xW[tid * 4 + 1] = f1;
                xW[tid * 4 + 2] = f2; xW[tid * 4 + 3] = f3;
            }
            if (tid < cnt && t + 2 < myhop) {
                int l = path[myb * ML + t + 2];
                float a = avail[myb * NL + l];
                float c = capa[myb * NL + l];
                f0 = a * inv_maxc; f1 = c * inv_maxc;
                f2 = a / c; f3 = loss[myb * NL + l];
            }

            unsigned long long acc2[6][SPT];
#pragma unroll
            for (int i = 0; i < 6; i++)
#pragma unroll
                for (int s = 0; s < SPT; s++) acc2[i][s] = 0ull;

            const ulonglong2* hsp = (const ulonglong2*)hR;
            const ulonglong2* wsp = (const ulonglong2*)wsh;
            const int sbase = sg * SPT * 32;
#pragma unroll 2
            for (int k4 = 0; k4 < 32; k4++) {
                ulonglong2 wv[6];
#pragma unroll
                for (int i = 0; i < 6; i++)
                    wv[i] = wsp[wbase4[i] + (k4 ^ jx[i])];
#pragma unroll
                for (int ss = 0; ss < SPT; ss++) {
                    ulonglong2 hv = hsp[sbase + ss * 32 + k4];
#pragma unroll
                    for (int i = 0; i < 6; i++) {
                        fma2(acc2[i][ss], wv[i].x, hv.x);
                        fma2(acc2[i][ss], wv[i].y, hv.y);
                    }
                }
            }

#pragma unroll
            for (int ss = 0; ss < SPT; ss++) {
                int s = sg * SPT + ss;
                int hp = shop[s];
                if (t < hp) {
                    float x0 = xR[s * 4 + 0], x1 = xR[s * 4 + 1];
                    float x2 = xR[s * 4 + 2], x3 = xR[s * 4 + 3];
#pragma unroll
                    for (int dd = 0; dd < 2; dd++) {
                        int d = jt + dd * 64;
                        int ir = dd * 3 + 0, iz = dd * 3 + 1, in_ = dd * 3 + 2;
                        float ar = upksum(acc2[ir][ss]);
                        float az = upksum(acc2[iz][ss]);
                        float an = upksum(acc2[in_][ss]);
                        float gr = bihv[ir] + wih[ir][0] * x0 + wih[ir][1] * x1
                                 + wih[ir][2] * x2 + wih[ir][3] * x3 + ar + bhhv[ir];
                        float gz = bihv[iz] + wih[iz][0] * x0 + wih[iz][1] * x1
                                 + wih[iz][2] * x2 + wih[iz][3] * x3 + az + bhhv[iz];
                        float gni = bihv[in_] + wih[in_][0] * x0 + wih[in_][1] * x1
                                  + wih[in_][2] * x2 + wih[in_][3] * x3;
                        float gnh = an + bhhv[in_];
                        float r = sigm(gr);
                        float z = sigm(gz);
                        float n = tanhap(gni + r * gnh);
                        float hold = hR[s * DP + d];
                        float hnew = (1.f - z) * n + z * hold;
                        hW[s * DP + d] = hnew;
                        if (t == hp - 1) {
                            g_flow[sb[s] * DP + d] = hnew;
                            bns[dd] += hnew;
                            bnq[dd] += hnew * hnew;
                        }
                    }
                }
            }
            __syncthreads();
        }
    }

    int slot = ((int)blockIdx.x * 4 + sg) * DP;
    g_psum[slot + jt]      = bns[0];
    g_psum[slot + jt + 64] = bns[1];
    g_psumsq[slot + jt]      = bnq[0];
    g_psumsq[slot + jt + 64] = bnq[1];
}

// ---------------- BN final ----------------
__global__ void k_bnfinal(const float* __restrict__ gamma, const float* __restrict__ beta) {
    __shared__ float ssum[8 * DP];
    __shared__ float ssq[8 * DP];
    int tid = threadIdx.x;
    int d = tid & 127;
    int seg = tid >> 7;
    float s = 0.f, s2 = 0.f;
    for (int blk = seg; blk < NPART; blk += 8) {
        s += g_psum[blk * DP + d];
        s2 += g_psumsq[blk * DP + d];
    }
    ssum[seg * DP + d] = s;
    ssq[seg * DP + d] = s2;
    __syncthreads();
    if (tid < DP) {
        float ts = 0.f, ts2 = 0.f;
#pragma unroll
        for (int g = 0; g < 8; g++) {
            ts += ssum[g * DP + tid];
            ts2 += ssq[g * DP + tid];
        }
        float mean = ts * (1.f / BS);
        float var = ts2 * (1.f / BS) - mean * mean;
        float rstd = rsqrtf(var + 1e-5f);
        float A = rstd * gamma[tid];
        g_bnA[tid] = A;
        g_bnB[tid] = beta[tid] - mean * A;
    }
}

// ---------------- fused readout, 64x256, cp.async double-buffered B ----------------
// smem: h1p 67584 | Bs ring 2x16384 | As(4096) union red(8192) => 108544 B
#define RD_SMEM (67584 + 32768 + 8192)
__global__ void __launch_bounds__(256, 2)
k_read(const float* __restrict__ rW1, const float* __restrict__ rb1,
       const float* __restrict__ rW2, const float* __restrict__ rb2,
       const float* __restrict__ rW3, const float* __restrict__ rb3,
       float* __restrict__ out) {
    extern __shared__ char smraw[];
    unsigned long long* h1p = (unsigned long long*)smraw;          // 256*33 ull
    float* Bs0 = (float*)(smraw + 67584);                          // 16*256 f
    float* Bs1 = (float*)(smraw + 67584 + 16384);                  // 16*256 f
    float* As  = (float*)(smraw + 67584 + 32768);                  // 16*64 f (phase 1)
    float* red = (float*)(smraw + 67584 + 32768);                  // 64*32 f (epilogue)

    int tid = threadIdx.x;
    int m0 = blockIdx.x * 64, u = blockIdx.y;
    int trow = tid >> 5, tcol = tid & 31;

    unsigned bs_sm[2] = { smaddr(Bs0), smaddr(Bs1) };
    float* bs_ptr[2] = { Bs0, Bs1 };

    // per-thread B staging coordinates (4 x 16B segments)
    int bk[4], bn4[4];
#pragma unroll
    for (int r = 0; r < 4; r++) {
        int idx = r * 256 + tid;
        bk[r] = idx >> 6;
        bn4[r] = (idx & 63) * 4;
    }

    unsigned long long acc2[4][8];
#pragma unroll
    for (int i = 0; i < 4; i++)
#pragma unroll
        for (int j = 0; j < 8; j++) acc2[i][j] = 0ull;

    const int am = tid >> 2, akq = tid & 3;

    // ================= phase 1: h1 = selu(BN(flow) @ rW1 + rb1) =================
    const float* B1 = rW1 + u * DP * DR;
#pragma unroll
    for (int r = 0; r < 4; r++)
        cpasync16(bs_sm[0] + (bk[r] * 256 + bn4[r]) * 4, B1 + bk[r] * DR + bn4[r]);
    cpcommit();
    float4 areg = *(const float4*)(g_flow + (m0 + am) * DP + akq * 4);

#pragma unroll 1
    for (int i = 0; i < 8; i++) {
        if (i < 7) {   // stage B chunk i+1 into the other buffer
            int k0n = (i + 1) * 16;
            unsigned dst = bs_sm[(i + 1) & 1];
#pragma unroll
            for (int r = 0; r < 4; r++)
                cpasync16(dst + (bk[r] * 256 + bn4[r]) * 4,
                          B1 + (k0n + bk[r]) * DR + bn4[r]);
            cpcommit();
        }
        {   // STS A chunk i with BN
            int kb = i * 16 + akq * 4;
            As[(akq * 4 + 0) * 64 + am] = areg.x * g_bnA[kb + 0] + g_bnB[kb + 0];
            As[(akq * 4 + 1) * 64 + am] = areg.y * g_bnA[kb + 1] + g_bnB[kb + 1];
            As[(akq * 4 + 2) * 64 + am] = areg.z * g_bnA[kb + 2] + g_bnB[kb + 2];
            As[(akq * 4 + 3) * 64 + am] = areg.w * g_bnA[kb + 3] + g_bnB[kb + 3];
        }
        if (i < 7)   // prefetch A chunk i+1 (latency hidden by FMA below)
            areg = *(const float4*)(g_flow + (m0 + am) * DP + (i + 1) * 16 + akq * 4);
        if (i < 7) cpwait1(); else cpwait0();
        __syncthreads();

        const float* Bc = bs_ptr[i & 1];
#pragma unroll
        for (int kk = 0; kk < 16; kk++) {
            ulonglong2 a01 = *(const ulonglong2*)&As[kk * 64 + trow * 8];
            ulonglong2 a23 = *(const ulonglong2*)&As[kk * 64 + trow * 8 + 4];
            unsigned long long ap[4] = {a01.x, a01.y, a23.x, a23.y};
#pragma unroll
            for (int jj = 0; jj < 4; jj++) {
                float2 bv = *(const float2*)&Bc[kk * 256 + tcol * 2 + 64 * jj];
                unsigned long long bx = splat(bv.x), by = splat(bv.y);
#pragma unroll
                for (int mp = 0; mp < 4; mp++) {
                    fma2(acc2[mp][jj * 2 + 0], ap[mp], bx);
                    fma2(acc2[mp][jj * 2 + 1], ap[mp], by);
                }
            }
        }
        __syncthreads();
    }
    // epilogue: selu + pack into h1p
#pragma unroll
    for (int mp = 0; mp < 4; mp++) {
#pragma unroll
        for (int j = 0; j < 8; j++) {
            int c = tcol * 2 + 64 * (j >> 1) + (j & 1);
            float b = rb1[u * DR + c];
            float lo = seluf(upklo(acc2[mp][j]) + b);
            float hi = seluf(upkhi(acc2[mp][j]) + b);
            h1p[c * 33 + trow * 4 + mp] = pk(lo, hi);
        }
    }
    __syncthreads();

    // ================= phase 2: h2 = selu(h1 @ rW2 + rb2); y = h2 . rW3 =================
    const float* B2 = rW2 + u * DR * DR;
    float w3v[8];
#pragma unroll
    for (int j = 0; j < 8; j++)
        w3v[j] = __ldg(rW3 + u * DR + tcol * 2 + 64 * (j >> 1) + (j & 1));

#pragma unroll
    for (int i = 0; i < 4; i++)
#pragma unroll
        for (int j = 0; j < 8; j++) acc2[i][j] = 0ull;

#pragma unroll
    for (int r = 0; r < 4; r++)
        cpasync16(bs_sm[0] + (bk[r] * 256 + bn4[r]) * 4, B2 + bk[r] * DR + bn4[r]);
    cpcommit();

#pragma unroll 1
    for (int i = 0; i < 16; i++) {
        if (i < 15) {
            int k0n = (i + 1) * 16;
            unsigned dst = bs_sm[(i + 1) & 1];
#pragma unroll
            for (int r = 0; r < 4; r++)
                cpasync16(dst + (bk[r] * 256 + bn4[r]) * 4,
                          B2 + (k0n + bk[r]) * DR + bn4[r]);
            cpcommit();
        }
        if (i < 15) cpwait1(); else cpwait0();
        __syncthreads();

        const float* Bc = bs_ptr[i & 1];
        const int kgb = i * 16;
#pragma unroll
        for (int kk = 0; kk < 16; kk++) {
            int kg = kgb + kk;
            // scalar 64-bit loads: h1p + kg*33 is only 8B-aligned (kg odd)
            unsigned long long ap[4];
#pragma unroll
            for (int mp = 0; mp < 4; mp++)
                ap[mp] = h1p[kg * 33 + trow * 4 + mp];   // warp broadcast
#pragma unroll
            for (int jj = 0; jj < 4; jj++) {
                float2 bv = *(const float2*)&Bc[kk * 256 + tcol * 2 + 64 * jj];
                unsigned long long bx = splat(bv.x), by = splat(bv.y);
#pragma unroll
                for (int mp = 0; mp < 4; mp++) {
                    fma2(acc2[mp][jj * 2 + 0], ap[mp], bx);
                    fma2(acc2[mp][jj * 2 + 1], ap[mp], by);
                }
            }
        }
        __syncthreads();
    }
    // epilogue: selu + dot w3 + block reduce (red overlaps As; phase 1 done)
#pragma unroll
    for (int mp = 0; mp < 4; mp++) {
#pragma unroll
        for (int e = 0; e < 2; e++) {
            int i = trow * 8 + mp * 2 + e;
            float p = 0.f;
#pragma unroll
            for (int j = 0; j < 8; j++) {
                int c = tcol * 2 + 64 * (j >> 1) + (j & 1);
                float v = e ? upkhi(acc2[mp][j]) : upklo(acc2[mp][j]);
                float h2 = seluf(v + rb2[u * DR + c]);
                p += h2 * w3v[j];
            }
            red[i * 32 + tcol] = p;
        }
    }
    __syncthreads();
    if (tid < 64) {
        float y = rb3[u];
#pragma unroll
        for (int c = 0; c < 32; c++) y += red[tid * 32 + c];
        out[(m0 + tid) * NO + u] = y;
    }
}

// ---------------- launcher ----------------
extern "C" void kernel_launch(void* const* d_in, const int* in_sizes, int n_in,
                              void* d_out, int out_size) {
    const float* demand = (const float*)d_in[0];
    const float* avail  = (const float*)d_in[1];
    const float* capa   = (const float*)d_in[2];
    const float* loss   = (const float*)d_in[3];
    const int*   path   = (const int*)d_in[4];
    const int*   hop    = (const int*)d_in[5];
    const float* w_ih   = (const float*)d_in[6];
    const float* w_hh   = (const float*)d_in[7];
    const float* b_ih   = (const float*)d_in[8];
    const float* b_hh   = (const float*)d_in[9];
    const float* gamma  = (const float*)d_in[10];
    const float* beta   = (const float*)d_in[11];
    const float* rW1    = (const float*)d_in[12];
    const float* rb1    = (const float*)d_in[13];
    const float* rW2    = (const float*)d_in[14];
    const float* rb2    = (const float*)d_in[15];
    const float* rW3    = (const float*)d_in[16];
    const float* rb3    = (const float*)d_in[17];
    float* out = (float*)d_out;

    const int GRU_SMEM = (49152 + 2 * BT * DP + 2 * BT * 4) * 4
                       + (2 * BT + 1) * 4 + 256;
    cudaFuncSetAttribute(k_gru, cudaFuncAttributeMaxDynamicSharedMemorySize, GRU_SMEM);
    cudaFuncSetAttribute(k_read, cudaFuncAttributeMaxDynamicSharedMemorySize, RD_SMEM);

    k_maxprep<<<257, 256>>>(capa, hop);                    // idx 0
    k_gru<<<GRU_BLOCKS, GRU_THREADS, GRU_SMEM>>>(          // idx 1
        demand, avail, capa, loss, path, hop, w_ih, w_hh, b_ih, b_hh);
    k_bnfinal<<<1, 1024>>>(gamma, beta);                   // idx 2
    {
        dim3 gr(BS / 64, NO);
        k_read<<<gr, 256, RD_SMEM>>>(rW1, rb1, rW2, rb2, rW3, rb3, out);  // idx 3
    }
}